// round 15
// baseline (speedup 1.0000x reference)
#include <cuda_runtime.h>
#include <cuda_fp16.h>

// Problem constants (fixed shapes for this dataset)
#define NN   2000
#define EE   32000
#define ETOT (EE + NN)      // edges + self loops
#define GG   32             // B*D
#define HH   4
#define CC   32
#define HC   128            // H*C
#define EMBD 32
#define NEG_SLOPE 0.2f
#define HB   32             // histogram blocks

// Scratch (device globals — no runtime allocation allowed).
__device__ __half  g_htab[NN * HC];       // fp16 features per token [tok*128+c*4+h]
__device__ float4  g_astab[NN];           // a_src logits per token (4 heads)
__device__ float4  g_adtab[NN];           // a_dst logits per token
__device__ int     g_degP[HB * 2048];     // per-block private histograms
__device__ int     g_off[NN + 1];
__device__ int     g_cur[NN];
__device__ int     g_csr[ETOT];           // src node per edge, grouped by dst
__device__ float4  g_alpha[(size_t)GG * ETOT];  // unnormalized exp-weights
__device__ int     g_ro[(size_t)GG * ETOT];     // feature-row byte offset

__device__ __forceinline__ float lrelu(float v) {
    return fmaxf(v, NEG_SLOPE * v);       // exact leaky-relu, branchless
}

// ============================================================================
// k_prep: blocks 0..249 = token tables (one warp per token);
//         blocks 250..281 = private edge-dst histograms (1000 edges each,
//         smem-private, no cross-block atomics, no global zeroing needed).
// ============================================================================
__global__ void __launch_bounds__(256) k_prep(
        const int* __restrict__ adj,
        const float* __restrict__ emb,
        const float* __restrict__ lw,
        const float* __restrict__ att_s,
        const float* __restrict__ att_d) {
    __shared__ union {
        struct { float w[EMBD * HC]; float as[HC]; float ad[HC]; } e;  // 17408 B
        int h[2048];
    } sh;
    int t = threadIdx.x;

    if (blockIdx.x >= 250) {
        // ---------------- private histogram over this block's 1000 edges ----
        int b = blockIdx.x - 250;                       // 0..31
        for (int i = t; i < 2048; i += 256) sh.h[i] = 0;
        __syncthreads();
        const int4* d4 = (const int4*)(adj + EE) + b * 250;
        if (t < 250) {
            int4 v = d4[t];
            atomicAdd(&sh.h[v.x], 1);
            atomicAdd(&sh.h[v.y], 1);
            atomicAdd(&sh.h[v.z], 1);
            atomicAdd(&sh.h[v.w], 1);
        }
        __syncthreads();
        int4* outp = (int4*)&g_degP[b * 2048];
        const int4* hp = (const int4*)sh.h;
        for (int i = t; i < 512; i += 256) outp[i] = hp[i];
        return;
    }

    // ---------------- token tables: features + attention logits -------------
    for (int i = t; i < EMBD * HC; i += 256) sh.e.w[i] = lw[i];
    if (t < HC) { sh.e.as[t] = att_s[t]; sh.e.ad[t] = att_d[t]; }
    __syncthreads();

    int tok  = blockIdx.x * 8 + (t >> 5);   // token id 0..1999
    int lane = t & 31;

    float ev = emb[tok * EMBD + lane];

    float a0 = 0.f, a1 = 0.f, a2 = 0.f, a3 = 0.f;
    #pragma unroll
    for (int l = 0; l < 32; l++) {
        float e = __shfl_sync(0xffffffffu, ev, l);
        const float* wr = &sh.e.w[l * HC];
        a0 = fmaf(e, wr[lane],      a0);
        a1 = fmaf(e, wr[32 + lane], a1);
        a2 = fmaf(e, wr[64 + lane], a2);
        a3 = fmaf(e, wr[96 + lane], a3);
    }

    __half2 p01 = __floats2half2_rn(a0, a1);
    __half2 p23 = __floats2half2_rn(a2, a3);
    uint2 raw;
    raw.x = *(const unsigned*)&p01;
    raw.y = *(const unsigned*)&p23;
    *(uint2*)&g_htab[tok * HC + lane * 4] = raw;

    float s0 = a0 * sh.e.as[lane],      s1 = a1 * sh.e.as[32 + lane];
    float s2 = a2 * sh.e.as[64 + lane], s3 = a3 * sh.e.as[96 + lane];
    float d0 = a0 * sh.e.ad[lane],      d1 = a1 * sh.e.ad[32 + lane];
    float d2 = a2 * sh.e.ad[64 + lane], d3 = a3 * sh.e.ad[96 + lane];
    #pragma unroll
    for (int o = 16; o > 0; o >>= 1) {
        s0 += __shfl_xor_sync(0xffffffffu, s0, o);
        s1 += __shfl_xor_sync(0xffffffffu, s1, o);
        s2 += __shfl_xor_sync(0xffffffffu, s2, o);
        s3 += __shfl_xor_sync(0xffffffffu, s3, o);
        d0 += __shfl_xor_sync(0xffffffffu, d0, o);
        d1 += __shfl_xor_sync(0xffffffffu, d1, o);
        d2 += __shfl_xor_sync(0xffffffffu, d2, o);
        d3 += __shfl_xor_sync(0xffffffffu, d3, o);
    }
    if (lane == 0) {
        g_astab[tok] = make_float4(s0, s1, s2, s3);
        g_adtab[tok] = make_float4(d0, d1, d2, d3);
    }
}

// ============================================================================
// k_scan: single block. Sum the 32 private histograms (+1 self loop per node),
// exclusive-scan 2048 counters, write offsets, pre-place self loops.
// ============================================================================
__global__ void __launch_bounds__(256) k_scan() {
    __shared__ int wsum[8];
    int t = threadIdx.x;
    int base = t * 8;

    int d[8];
    {
        int4 acc0 = make_int4(0, 0, 0, 0), acc1 = make_int4(0, 0, 0, 0);
        #pragma unroll
        for (int b = 0; b < HB; b++) {
            const int4* P = (const int4*)&g_degP[b * 2048 + base];
            int4 u = P[0], v = P[1];
            acc0.x += u.x; acc0.y += u.y; acc0.z += u.z; acc0.w += u.w;
            acc1.x += v.x; acc1.y += v.y; acc1.z += v.z; acc1.w += v.w;
        }
        d[0] = acc0.x; d[1] = acc0.y; d[2] = acc0.z; d[3] = acc0.w;
        d[4] = acc1.x; d[5] = acc1.y; d[6] = acc1.z; d[7] = acc1.w;
        #pragma unroll
        for (int k = 0; k < 8; k++) if (base + k < NN) d[k] += 1;  // self loop
    }

    int loc[8]; int sum = 0;
    #pragma unroll
    for (int k = 0; k < 8; k++) { loc[k] = sum; sum += d[k]; }
    int lane = t & 31, wid = t >> 5;
    int v = sum;
    #pragma unroll
    for (int o = 1; o < 32; o <<= 1) {
        int n = __shfl_up_sync(0xffffffffu, v, o);
        if (lane >= o) v += n;
    }
    if (lane == 31) wsum[wid] = v;
    __syncthreads();
    if (t == 0) {
        int acc = 0;
        #pragma unroll
        for (int wi = 0; wi < 8; wi++) { int tmp = wsum[wi]; wsum[wi] = acc; acc += tmp; }
    }
    __syncthreads();
    int excl = v - sum + wsum[wid];
    #pragma unroll
    for (int k = 0; k < 8; k++) {
        int i = base + k;
        int e = excl + loc[k];
        if (i <= NN) g_off[i] = e;
        if (i < NN) { g_csr[e] = i; g_cur[i] = e + 1; }   // self loop first
    }
}

// ============================================================================
// k_scatter: parallel CSR scatter via gmem atomics.
// ============================================================================
__global__ void __launch_bounds__(256) k_scatter(const int* __restrict__ adj) {
    int i = blockIdx.x * 256 + threadIdx.x;       // one int4 per thread
    if (i >= EE / 4) return;
    int4 s = ((const int4*)adj)[i];
    int4 d = ((const int4*)(adj + EE))[i];
    g_csr[atomicAdd(&g_cur[d.x], 1)] = s.x;
    g_csr[atomicAdd(&g_cur[d.y], 1)] = s.y;
    g_csr[atomicAdd(&g_cur[d.z], 1)] = s.z;
    g_csr[atomicAdd(&g_cur[d.w], 1)] = s.w;
}

// ============================================================================
// k_alpha: one warp per (g,dst). Lane j computes edge j's exp-weights ONCE,
// stores {p4, row byte-offset}. No reduction (k_agg sums denominators inline).
// No max-subtraction (logits O(+-8); softmax shift-invariant; no overflow).
// ============================================================================
__global__ void __launch_bounds__(256) k_alpha(const int* __restrict__ x) {
    int wslot = threadIdx.x >> 5;
    int lane  = threadIdx.x & 31;
    int warp  = blockIdx.x * 8 + wslot;
    int g   = warp / NN;
    int dst = warp - g * NN;
    const int* xg = x + g * NN;

    float4 adh = g_adtab[xg[dst]];
    int beg = g_off[dst], end = g_off[dst + 1];
    int gb  = g * ETOT;

    for (int j0 = beg; j0 < end; j0 += 32) {
        int j = j0 + lane;
        if (j < end) {
            int tok = xg[g_csr[j]];
            float4 as = g_astab[tok];
            float4 p;
            p.x = __expf(lrelu(as.x + adh.x));
            p.y = __expf(lrelu(as.y + adh.y));
            p.z = __expf(lrelu(as.z + adh.z));
            p.w = __expf(lrelu(as.w + adh.w));
            g_alpha[gb + j] = p;
            g_ro[gb + j]    = tok * (HC * 2);   // byte offset of fp16 row
        }
    }
}

// ============================================================================
// k_agg: one warp per (g,dst). Half-warp pairing (2 edges/iter) + SOFTWARE
// PIPELINE: next pair's {pk, ro} and its feature LDG issue before the current
// pair is consumed -> two dependent chains in flight. Denominator accumulated
// inline (s += pk), merged with the same shfl(16) as the features.
// ============================================================================
__global__ void __launch_bounds__(256) k_agg(float* __restrict__ out,
                                             const float* __restrict__ bias) {
    int wslot = threadIdx.x >> 5;
    int lane  = threadIdx.x & 31;
    int hw    = lane >> 4;
    int hl    = lane & 15;
    int warp  = blockIdx.x * 8 + wslot;
    int g   = warp / NN;
    int dst = warp - g * NN;

    int beg = g_off[dst];
    int cnt = g_off[dst + 1] - beg;
    int eb  = g * ETOT + beg;
    const float4* pp = g_alpha + eb;
    const int*    rp = g_ro    + eb;
    const char* hbase = (const char*)g_htab + hl * 16;   // lane's 16B slice

    float s0 = 0.f, s1 = 0.f, s2 = 0.f, s3 = 0.f;   // per-half denominators
    float c0 = 0.f, c1 = 0.f, c2 = 0.f, c3 = 0.f;   // c=2*hl,   h=0..3
    float c4 = 0.f, c5 = 0.f, c6 = 0.f, c7 = 0.f;   // c=2*hl+1, h=0..3

    int pairs = cnt >> 1;
    if (pairs > 0) {
        float4 pk = pp[hw];
        int    ro = rp[hw];
        uint4 raw = *(const uint4*)(hbase + ro);
        #pragma unroll 2
        for (int it = 1; it < pairs; it++) {
            int k = it * 2 + hw;
            float4 pk_n = pp[k];                      // prefetch next pair
            int    ro_n = rp[k];
            uint4 raw_n = *(const uint4*)(hbase + ro_n);
            s0 += pk.x; s1 += pk.y; s2 += pk.z; s3 += pk.w;
            float2 f0 = __half22float2(*(const __half2*)&raw.x);
            float2 f1 = __half22float2(*(const __half2*)&raw.y);
            float2 f2 = __half22float2(*(const __half2*)&raw.z);
            float2 f3 = __half22float2(*(const __half2*)&raw.w);
            c0 = fmaf(pk.x, f0.x, c0);
            c1 = fmaf(pk.y, f0.y, c1);
            c2 = fmaf(pk.z, f1.x, c2);
            c3 = fmaf(pk.w, f1.y, c3);
            c4 = fmaf(pk.x, f2.x, c4);
            c5 = fmaf(pk.y, f2.y, c5);
            c6 = fmaf(pk.z, f3.x, c6);
            c7 = fmaf(pk.w, f3.y, c7);
            pk = pk_n; raw = raw_n;
        }
        s0 += pk.x; s1 += pk.y; s2 += pk.z; s3 += pk.w;
        float2 f0 = __half22float2(*(const __half2*)&raw.x);
        float2 f1 = __half22float2(*(const __half2*)&raw.y);
        float2 f2 = __half22float2(*(const __half2*)&raw.z);
        float2 f3 = __half22float2(*(const __half2*)&raw.w);
        c0 = fmaf(pk.x, f0.x, c0);
        c1 = fmaf(pk.y, f0.y, c1);
        c2 = fmaf(pk.z, f1.x, c2);
        c3 = fmaf(pk.w, f1.y, c3);
        c4 = fmaf(pk.x, f2.x, c4);
        c5 = fmaf(pk.y, f2.y, c5);
        c6 = fmaf(pk.z, f3.x, c6);
        c7 = fmaf(pk.w, f3.y, c7);
    }
    if ((cnt & 1) && hw == 0) {                       // odd tail: half 0 only
        int k = cnt - 1;
        float4 pk = pp[k];
        int    ro = rp[k];
        uint4 raw = *(const uint4*)(hbase + ro);
        s0 += pk.x; s1 += pk.y; s2 += pk.z; s3 += pk.w;
        float2 f0 = __half22float2(*(const __half2*)&raw.x);
        float2 f1 = __half22float2(*(const __half2*)&raw.y);
        float2 f2 = __half22float2(*(const __half2*)&raw.z);
        float2 f3 = __half22float2(*(const __half2*)&raw.w);
        c0 = fmaf(pk.x, f0.x, c0);
        c1 = fmaf(pk.y, f0.y, c1);
        c2 = fmaf(pk.z, f1.x, c2);
        c3 = fmaf(pk.w, f1.y, c3);
        c4 = fmaf(pk.x, f2.x, c4);
        c5 = fmaf(pk.y, f2.y, c5);
        c6 = fmaf(pk.z, f3.x, c6);
        c7 = fmaf(pk.w, f3.y, c7);
    }

    // merge the two half-warp partials (each half saw different edges)
    c0 += __shfl_xor_sync(0xffffffffu, c0, 16);
    c1 += __shfl_xor_sync(0xffffffffu, c1, 16);
    c2 += __shfl_xor_sync(0xffffffffu, c2, 16);
    c3 += __shfl_xor_sync(0xffffffffu, c3, 16);
    c4 += __shfl_xor_sync(0xffffffffu, c4, 16);
    c5 += __shfl_xor_sync(0xffffffffu, c5, 16);
    c6 += __shfl_xor_sync(0xffffffffu, c6, 16);
    c7 += __shfl_xor_sync(0xffffffffu, c7, 16);
    s0 += __shfl_xor_sync(0xffffffffu, s0, 16);
    s1 += __shfl_xor_sync(0xffffffffu, s1, 16);
    s2 += __shfl_xor_sync(0xffffffffu, s2, 16);
    s3 += __shfl_xor_sync(0xffffffffu, s3, 16);

    // write: half 0 -> heads 0,1 ; half 1 -> heads 2,3. Lane owns c=2hl,2hl+1.
    float* orow = out + (size_t)warp * HC;
    int h0 = hw * 2, h1 = hw * 2 + 1;
    float i0 = __frcp_rn((hw == 0) ? s0 : s2);
    float i1 = __frcp_rn((hw == 0) ? s1 : s3);
    float wa0 = ((hw == 0) ? c0 : c2) * i0;   // (c=2hl,   head h0)
    float wb0 = ((hw == 0) ? c4 : c6) * i0;   // (c=2hl+1, head h0)
    float wa1 = ((hw == 0) ? c1 : c3) * i1;   // (c=2hl,   head h1)
    float wb1 = ((hw == 0) ? c5 : c7) * i1;   // (c=2hl+1, head h1)
    const float2* b2 = (const float2*)bias;
    float2 ba = b2[h0 * 16 + hl];
    float2 bb = b2[h1 * 16 + hl];
    *(float2*)&orow[h0 * 32 + hl * 2] = make_float2(wa0 + ba.x, wb0 + ba.y);
    *(float2*)&orow[h1 * 32 + hl * 2] = make_float2(wa1 + bb.x, wb1 + bb.y);
}

// ------------------------------------------------------------------ launch
extern "C" void kernel_launch(void* const* d_in, const int* in_sizes, int n_in,
                              void* d_out, int out_size) {
    const int*   x    = (const int*)d_in[0];
    const int*   adj  = (const int*)d_in[1];
    const float* emb  = (const float*)d_in[2];
    const float* lw   = (const float*)d_in[3];
    const float* ats  = (const float*)d_in[4];
    const float* atd  = (const float*)d_in[5];
    const float* bias = (const float*)d_in[6];
    float* out = (float*)d_out;

    k_prep<<<250 + HB, 256>>>(adj, emb, lw, ats, atd);
    k_scan<<<1, 256>>>();
    k_scatter<<<(EE / 4 + 255) / 256, 256>>>(adj);
    k_alpha<<<(GG * NN) / 8, 256>>>(x);
    k_agg<<<(GG * NN) / 8, 256>>>(out, bias);
}

// round 16
// speedup vs baseline: 1.2436x; 1.2436x over previous
#include <cuda_runtime.h>
#include <cuda_fp16.h>

// Problem constants (fixed shapes for this dataset)
#define NN   2000
#define EE   32000
#define ETOT (EE + NN)      // edges + self loops
#define GG   32             // B*D
#define HH   4
#define CC   32
#define HC   128            // H*C
#define EMBD 32
#define NEG_SLOPE 0.2f

// Scratch (device globals — no runtime allocation allowed).
__device__ __half  g_htab[NN * HC];       // fp16 features per token [tok*128+c*4+h]
__device__ float4  g_astab[NN];           // a_src logits per token (4 heads)
__device__ float4  g_adtab[NN];           // a_dst logits per token
__device__ int     g_off[NN + 1];
__device__ int     g_cur[NN];
__device__ int     g_csr[ETOT];           // src node per edge, grouped by dst
__device__ int     g_edst[ETOT];          // dst node per edge (same grouping)
__device__ float4  g_alpha[(size_t)GG * ETOT];  // unnormalized exp-weights
__device__ int     g_ro[(size_t)GG * ETOT];     // feature-row byte offset

__device__ __forceinline__ float lrelu(float v) {
    return fmaxf(v, NEG_SLOPE * v);       // exact leaky-relu, branchless
}

// ============================================================================
// k_prep: block 0 = histogram + scan (CSR offsets, self-loops pre-placed);
//         blocks 1..250 = token tables (one warp per token).
// ============================================================================
__global__ void __launch_bounds__(256) k_prep(
        const int* __restrict__ adj,
        const float* __restrict__ emb,
        const float* __restrict__ lw,
        const float* __restrict__ att_s,
        const float* __restrict__ att_d) {
    __shared__ union {
        struct { float w[EMBD * HC]; float as[HC]; float ad[HC]; } e;  // 17408 B
        struct { int deg[2048]; int wsum[8]; } c;
    } sh;
    int t = threadIdx.x;

    if (blockIdx.x == 0) {
        // deg starts at 1: every node has exactly one self loop.
        for (int i = t; i < 2048; i += 256) sh.c.deg[i] = (i < NN) ? 1 : 0;
        __syncthreads();
        const int4* d4 = (const int4*)(adj + EE);
        for (int i = t; i < EE / 4; i += 256) {
            int4 v = d4[i];
            atomicAdd(&sh.c.deg[v.x], 1);
            atomicAdd(&sh.c.deg[v.y], 1);
            atomicAdd(&sh.c.deg[v.z], 1);
            atomicAdd(&sh.c.deg[v.w], 1);
        }
        __syncthreads();
        // exclusive scan over 2048 counters: 8/thread + warp scan + partials
        int base = t * 8;
        int loc[8]; int sum = 0;
        #pragma unroll
        for (int k = 0; k < 8; k++) { loc[k] = sum; sum += sh.c.deg[base + k]; }
        int lane = t & 31, wid = t >> 5;
        int v = sum;
        #pragma unroll
        for (int o = 1; o < 32; o <<= 1) {
            int n = __shfl_up_sync(0xffffffffu, v, o);
            if (lane >= o) v += n;
        }
        if (lane == 31) sh.c.wsum[wid] = v;
        __syncthreads();
        if (t == 0) {
            int acc = 0;
            #pragma unroll
            for (int wi = 0; wi < 8; wi++) {
                int tmp = sh.c.wsum[wi]; sh.c.wsum[wi] = acc; acc += tmp;
            }
        }
        __syncthreads();
        int excl = v - sum + sh.c.wsum[wid];
        #pragma unroll
        for (int k = 0; k < 8; k++) {
            int i = base + k;
            int e = excl + loc[k];
            if (i <= NN) g_off[i] = e;
            if (i < NN) {                       // self loop first in segment
                g_csr[e]  = i;
                g_edst[e] = i;
                g_cur[i]  = e + 1;
            }
        }
        return;
    }

    // ---------------- token tables: features + attention logits -------------
    for (int i = t; i < EMBD * HC; i += 256) sh.e.w[i] = lw[i];
    if (t < HC) { sh.e.as[t] = att_s[t]; sh.e.ad[t] = att_d[t]; }
    __syncthreads();

    int tok  = (blockIdx.x - 1) * 8 + (t >> 5);   // token id 0..1999
    int lane = t & 31;

    float ev = emb[tok * EMBD + lane];

    float a0 = 0.f, a1 = 0.f, a2 = 0.f, a3 = 0.f;
    #pragma unroll
    for (int l = 0; l < 32; l++) {
        float e = __shfl_sync(0xffffffffu, ev, l);
        const float* wr = &sh.e.w[l * HC];
        a0 = fmaf(e, wr[lane],      a0);
        a1 = fmaf(e, wr[32 + lane], a1);
        a2 = fmaf(e, wr[64 + lane], a2);
        a3 = fmaf(e, wr[96 + lane], a3);
    }

    __half2 p01 = __floats2half2_rn(a0, a1);
    __half2 p23 = __floats2half2_rn(a2, a3);
    uint2 raw;
    raw.x = *(const unsigned*)&p01;
    raw.y = *(const unsigned*)&p23;
    *(uint2*)&g_htab[tok * HC + lane * 4] = raw;

    float s0 = a0 * sh.e.as[lane],      s1 = a1 * sh.e.as[32 + lane];
    float s2 = a2 * sh.e.as[64 + lane], s3 = a3 * sh.e.as[96 + lane];
    float d0 = a0 * sh.e.ad[lane],      d1 = a1 * sh.e.ad[32 + lane];
    float d2 = a2 * sh.e.ad[64 + lane], d3 = a3 * sh.e.ad[96 + lane];
    #pragma unroll
    for (int o = 16; o > 0; o >>= 1) {
        s0 += __shfl_xor_sync(0xffffffffu, s0, o);
        s1 += __shfl_xor_sync(0xffffffffu, s1, o);
        s2 += __shfl_xor_sync(0xffffffffu, s2, o);
        s3 += __shfl_xor_sync(0xffffffffu, s3, o);
        d0 += __shfl_xor_sync(0xffffffffu, d0, o);
        d1 += __shfl_xor_sync(0xffffffffu, d1, o);
        d2 += __shfl_xor_sync(0xffffffffu, d2, o);
        d3 += __shfl_xor_sync(0xffffffffu, d3, o);
    }
    if (lane == 0) {
        g_astab[tok] = make_float4(s0, s1, s2, s3);
        g_adtab[tok] = make_float4(d0, d1, d2, d3);
    }
}

// ============================================================================
// k_scatter: parallel CSR scatter via gmem atomics; also records per-edge dst.
// ============================================================================
__global__ void __launch_bounds__(256) k_scatter(const int* __restrict__ adj) {
    int i = blockIdx.x * 256 + threadIdx.x;       // one int4 per thread
    if (i >= EE / 4) return;
    int4 s = ((const int4*)adj)[i];
    int4 d = ((const int4*)(adj + EE))[i];
    int p0 = atomicAdd(&g_cur[d.x], 1);
    int p1 = atomicAdd(&g_cur[d.y], 1);
    int p2 = atomicAdd(&g_cur[d.z], 1);
    int p3 = atomicAdd(&g_cur[d.w], 1);
    g_csr[p0] = s.x;  g_edst[p0] = d.x;
    g_csr[p1] = s.y;  g_edst[p1] = d.y;
    g_csr[p2] = s.z;  g_edst[p2] = d.z;
    g_csr[p3] = s.w;  g_edst[p3] = d.w;
}

// ============================================================================
// k_alpha: EDGE-PARALLEL — one thread per (g, edge-slot), 1.088M threads.
// Fully coalesced csr/edst loads and alpha/ro stores; table gathers are
// L1-resident. No idle lanes, no loops, no reductions.
// No max-subtraction (logits O(+-8); softmax shift-invariant; no overflow).
// ============================================================================
__global__ void __launch_bounds__(256) k_alpha(const int* __restrict__ x) {
    int i = blockIdx.x * 256 + threadIdx.x;
    if (i >= GG * ETOT) return;
    int g = i / ETOT;
    int e = i - g * ETOT;
    const int* xg = x + g * NN;

    int src  = g_csr[e];
    int dstn = g_edst[e];
    int ts = xg[src];
    int td = xg[dstn];
    float4 as = g_astab[ts];
    float4 ad = g_adtab[td];
    float4 p;
    p.x = __expf(lrelu(as.x + ad.x));
    p.y = __expf(lrelu(as.y + ad.y));
    p.z = __expf(lrelu(as.z + ad.z));
    p.w = __expf(lrelu(as.w + ad.w));
    g_alpha[i] = p;
    g_ro[i]    = ts * (HC * 2);               // byte offset of fp16 feature row
}

// ============================================================================
// k_agg: one warp per (g,dst). R13 loop structure (known 40.2us): half-warp
// pairing, broadcast LDG.128 weights + LDG.32 offset + LDG.128 feature slice,
// unroll 2. Denominator accumulated inline (s += pk), merged with the same
// shfl(16) as the features; reciprocal applied in the epilogue.
// ============================================================================
__global__ void __launch_bounds__(256) k_agg(float* __restrict__ out,
                                             const float* __restrict__ bias) {
    int wslot = threadIdx.x >> 5;
    int lane  = threadIdx.x & 31;
    int hw    = lane >> 4;
    int hl    = lane & 15;
    int warp  = blockIdx.x * 8 + wslot;
    int g   = warp / NN;
    int dst = warp - g * NN;

    int beg = g_off[dst];
    int cnt = g_off[dst + 1] - beg;
    int eb  = g * ETOT + beg;
    const float4* pp = g_alpha + eb;
    const int*    rp = g_ro    + eb;
    const char* hbase = (const char*)g_htab + hl * 16;   // lane's 16B slice

    float s0 = 0.f, s1 = 0.f, s2 = 0.f, s3 = 0.f;   // per-half denominators
    float c0 = 0.f, c1 = 0.f, c2 = 0.f, c3 = 0.f;   // c=2*hl,   h=0..3
    float c4 = 0.f, c5 = 0.f, c6 = 0.f, c7 = 0.f;   // c=2*hl+1, h=0..3

    int pairs = cnt >> 1;
    #pragma unroll 2
    for (int it = 0; it < pairs; it++) {
        int k = it * 2 + hw;
        float4 pk = pp[k];                            // LDG.128 bcast per half
        int    ro = rp[k];                            // LDG.32 bcast per half
        uint4 raw = *(const uint4*)(hbase + ro);      // LDG.128 feature slice
        s0 += pk.x; s1 += pk.y; s2 += pk.z; s3 += pk.w;
        float2 f0 = __half22float2(*(const __half2*)&raw.x);
        float2 f1 = __half22float2(*(const __half2*)&raw.y);
        float2 f2 = __half22float2(*(const __half2*)&raw.z);
        float2 f3 = __half22float2(*(const __half2*)&raw.w);
        c0 = fmaf(pk.x, f0.x, c0);
        c1 = fmaf(pk.y, f0.y, c1);
        c2 = fmaf(pk.z, f1.x, c2);
        c3 = fmaf(pk.w, f1.y, c3);
        c4 = fmaf(pk.x, f2.x, c4);
        c5 = fmaf(pk.y, f2.y, c5);
        c6 = fmaf(pk.z, f3.x, c6);
        c7 = fmaf(pk.w, f3.y, c7);
    }
    if ((cnt & 1) && hw == 0) {                       // odd tail: half 0 only
        int k = cnt - 1;
        float4 pk = pp[k];
        int    ro = rp[k];
        uint4 raw = *(const uint4*)(hbase + ro);
        s0 += pk.x; s1 += pk.y; s2 += pk.z; s3 += pk.w;
        float2 f0 = __half22float2(*(const __half2*)&raw.x);
        float2 f1 = __half22float2(*(const __half2*)&raw.y);
        float2 f2 = __half22float2(*(const __half2*)&raw.z);
        float2 f3 = __half22float2(*(const __half2*)&raw.w);
        c0 = fmaf(pk.x, f0.x, c0);
        c1 = fmaf(pk.y, f0.y, c1);
        c2 = fmaf(pk.z, f1.x, c2);
        c3 = fmaf(pk.w, f1.y, c3);
        c4 = fmaf(pk.x, f2.x, c4);
        c5 = fmaf(pk.y, f2.y, c5);
        c6 = fmaf(pk.z, f3.x, c6);
        c7 = fmaf(pk.w, f3.y, c7);
    }

    // merge the two half-warp partials (each half saw different edges)
    c0 += __shfl_xor_sync(0xffffffffu, c0, 16);
    c1 += __shfl_xor_sync(0xffffffffu, c1, 16);
    c2 += __shfl_xor_sync(0xffffffffu, c2, 16);
    c3 += __shfl_xor_sync(0xffffffffu, c3, 16);
    c4 += __shfl_xor_sync(0xffffffffu, c4, 16);
    c5 += __shfl_xor_sync(0xffffffffu, c5, 16);
    c6 += __shfl_xor_sync(0xffffffffu, c6, 16);
    c7 += __shfl_xor_sync(0xffffffffu, c7, 16);
    s0 += __shfl_xor_sync(0xffffffffu, s0, 16);
    s1 += __shfl_xor_sync(0xffffffffu, s1, 16);
    s2 += __shfl_xor_sync(0xffffffffu, s2, 16);
    s3 += __shfl_xor_sync(0xffffffffu, s3, 16);

    // write: half 0 -> heads 0,1 ; half 1 -> heads 2,3. Lane owns c=2hl,2hl+1.
    float* orow = out + (size_t)warp * HC;
    int h0 = hw * 2, h1 = hw * 2 + 1;
    float i0 = __frcp_rn((hw == 0) ? s0 : s2);
    float i1 = __frcp_rn((hw == 0) ? s1 : s3);
    float wa0 = ((hw == 0) ? c0 : c2) * i0;   // (c=2hl,   head h0)
    float wb0 = ((hw == 0) ? c4 : c6) * i0;   // (c=2hl+1, head h0)
    float wa1 = ((hw == 0) ? c1 : c3) * i1;   // (c=2hl,   head h1)
    float wb1 = ((hw == 0) ? c5 : c7) * i1;   // (c=2hl+1, head h1)
    const float2* b2 = (const float2*)bias;
    float2 ba = b2[h0 * 16 + hl];
    float2 bb = b2[h1 * 16 + hl];
    *(float2*)&orow[h0 * 32 + hl * 2] = make_float2(wa0 + ba.x, wb0 + ba.y);
    *(float2*)&orow[h1 * 32 + hl * 2] = make_float2(wa1 + bb.x, wb1 + bb.y);
}

// ------------------------------------------------------------------ launch
extern "C" void kernel_launch(void* const* d_in, const int* in_sizes, int n_in,
                              void* d_out, int out_size) {
    const int*   x    = (const int*)d_in[0];
    const int*   adj  = (const int*)d_in[1];
    const float* emb  = (const float*)d_in[2];
    const float* lw   = (const float*)d_in[3];
    const float* ats  = (const float*)d_in[4];
    const float* atd  = (const float*)d_in[5];
    const float* bias = (const float*)d_in[6];
    float* out = (float*)d_out;

    k_prep<<<1 + (NN + 7) / 8, 256>>>(adj, emb, lw, ats, atd);
    k_scatter<<<(EE / 4 + 255) / 256, 256>>>(adj);
    k_alpha<<<(GG * ETOT + 255) / 256, 256>>>(x);
    k_agg<<<(GG * NN) / 8, 256>>>(out, bias);
}